// round 1
// baseline (speedup 1.0000x reference)
#include <cuda_runtime.h>
#include <cuda_bf16.h>

// Activations / scratch in static device memory (sanctioned scratch path).
// Layouts: [location][channel/k][batch], batch innermost (4096).
__device__ float g_P0[400 * 54 * 4096];   // im2col of x: [loc0][k=54][B]   (354 MB)
__device__ float g_H0[400 * 32 * 4096];   // layer0 out:  [loc0][c=32][B]   (210 MB)
__device__ float g_H1[100 * 64 * 4096];   // layer1 out:  [loc1][c=64][B]   (105 MB)
__device__ float g_H2[4 * 128 * 4096];    // layer2 out:  [loc2][c=128][B]  (8.4 MB)

static __device__ __forceinline__ float tanhap(float x) {
    float y;
    asm("tanh.approx.f32 %0, %1;" : "=f"(y) : "f"(x));
    return y;
}

static __device__ __forceinline__ unsigned long long pack2(float w) {
    unsigned long long p;
    asm("mov.b64 %0, {%1, %1};" : "=l"(p) : "f"(w));
    return p;
}

static __device__ __forceinline__ void ffma2(unsigned long long& acc,
                                             unsigned long long a,
                                             unsigned long long w2) {
    asm("fma.rn.f32x2 %0, %1, %2, %0;" : "+l"(acc) : "l"(a), "l"(w2));
}

// ---------------------------------------------------------------------------
// im2col / transpose: x[B,6,60,60] -> g_P0[loc][k][B]
//   loc = (h/3)*20 + (w/3), k = c*9 + (h%3)*3 + (w%3)
// Block: one (c,h) row x 32-batch tile. smem-tiled transpose for coalescing
// on both sides.
// ---------------------------------------------------------------------------
__global__ void __launch_bounds__(256) im2col_k(const float* __restrict__ x) {
    const int ch = blockIdx.x;          // 0..359
    const int c = ch / 60, h = ch % 60;
    const int b0 = blockIdx.y * 32;

    __shared__ float s[32 * 61];        // [b_local][w], padded stride 61

    const float* src = x + ((size_t)b0 * 6 + c) * 3600 + (size_t)h * 60;
    for (int e = threadIdx.x; e < 32 * 60; e += 256) {
        int bl = e / 60;
        int w  = e - bl * 60;
        s[bl * 61 + w] = src[(size_t)bl * 21600 + w];
    }
    __syncthreads();

    const int i = h / 3, dh = h % 3;
    for (int e = threadIdx.x; e < 32 * 60; e += 256) {
        int w  = e >> 5;                // 0..59
        int bl = e & 31;
        int j = w / 3, dw = w - j * 3;
        int loc = i * 20 + j;
        int k = c * 9 + dh * 3 + dw;
        g_P0[((size_t)loc * 54 + k) * 4096 + b0 + bl] = s[bl * 61 + w];
    }
}

// ---------------------------------------------------------------------------
// Generic locally-connected GEMM layer (per-location GEMM over batch):
//   out[loc][co][b] = tanh( bias[loc][co] + sum_k W[loc][co][k] * A[loc][k][b] )
// where A row k maps into `in` at [loc_in(k)][cin(k)][b]  (kernel==stride).
// Block: 128 batches x COUT_BLK couts. 256 threads.
// Thread: lane = batch-pair selector, cgrp = cout group of NC=COUT_BLK/8.
// Packed f32x2 FMAs: 2 batches per instruction.
// ---------------------------------------------------------------------------
template <int CIN, int KH, int KW, int WIN, int WOUT, int COUT, int COUT_BLK, int KCHUNK>
static __device__ __forceinline__ void lc_gemm_body(const float* __restrict__ in,
                                                    const float* __restrict__ W,
                                                    const float* __restrict__ bias,
                                                    float* __restrict__ out) {
    constexpr int K  = CIN * KH * KW;
    constexpr int NC = COUT_BLK / 8;
    constexpr int B  = 4096;

    __shared__ __align__(16) float as[KCHUNK * 128];      // A tile [kc][b_local]
    __shared__ __align__(16) float ws[COUT_BLK * KCHUNK]; // W tile [co][kc]

    const int loc = blockIdx.x;
    const int i = loc / WOUT, j = loc - i * WOUT;
    const int b0 = blockIdx.y * 128;
    const int cz = blockIdx.z * COUT_BLK;
    const int t = threadIdx.x;
    const int lane = t & 31;
    const int cgrp = t >> 5;

    const float* Wl = W + ((size_t)loc * COUT + cz) * K;

    unsigned long long acc0[NC], acc1[NC];
#pragma unroll
    for (int c = 0; c < NC; c++) {
        float bv = bias[(size_t)loc * COUT + cz + cgrp * NC + c];
        unsigned long long p = pack2(bv);
        acc0[c] = p;
        acc1[c] = p;
    }

    for (int k0 = 0; k0 < K; k0 += KCHUNK) {
        // Load weight chunk: ws[co*KCHUNK + kc] = Wl[co*K + k0 + kc]  (coalesced)
        for (int idx = t; idx < COUT_BLK * KCHUNK; idx += 256) {
            int co = idx / KCHUNK;
            int kc = idx - co * KCHUNK;
            ws[idx] = Wl[(size_t)co * K + k0 + kc];
        }
        // Load A chunk: as[kc*128 + bl] = in[(loc_in*CIN + c)*B + b0 + bl]  (coalesced)
        for (int idx = t; idx < KCHUNK * 128; idx += 256) {
            int kc = idx >> 7;
            int bl = idx & 127;
            int k = k0 + kc;
            int c  = k / (KH * KW);
            int r  = k - c * (KH * KW);
            int dh = r / KW;
            int dw = r - dh * KW;
            int loc_in = (KH * i + dh) * WIN + (KW * j + dw);
            as[idx] = in[((size_t)loc_in * CIN + c) * B + b0 + bl];
        }
        __syncthreads();

        const unsigned long long* a2 = (const unsigned long long*)as;
#pragma unroll 2
        for (int kc = 0; kc < KCHUNK; kc++) {
            unsigned long long a0 = a2[kc * 64 + lane];        // batches 2*lane, 2*lane+1
            unsigned long long a1 = a2[kc * 64 + 32 + lane];   // batches 64+2*lane, +1
#pragma unroll
            for (int c = 0; c < NC; c++) {
                float w = ws[(cgrp * NC + c) * KCHUNK + kc];   // smem broadcast
                unsigned long long w2 = pack2(w);
                ffma2(acc0[c], a0, w2);
                ffma2(acc1[c], a1, w2);
            }
        }
        __syncthreads();
    }

#pragma unroll
    for (int c = 0; c < NC; c++) {
        float x0, x1, y0, y1;
        asm("mov.b64 {%0, %1}, %2;" : "=f"(x0), "=f"(x1) : "l"(acc0[c]));
        asm("mov.b64 {%0, %1}, %2;" : "=f"(y0), "=f"(y1) : "l"(acc1[c]));
        x0 = tanhap(x0); x1 = tanhap(x1);
        y0 = tanhap(y0); y1 = tanhap(y1);
        size_t ob = ((size_t)loc * COUT + cz + cgrp * NC + c) * B + b0;
        ((float2*)(out + ob))[lane]      = make_float2(x0, x1);
        ((float2*)(out + ob + 64))[lane] = make_float2(y0, y1);
    }
}

// Layer wrappers (reference the static scratch buffers directly; no host symbol
// lookups needed).
__global__ void __launch_bounds__(256) k_l0(const float* __restrict__ W,
                                            const float* __restrict__ b) {
    // L0 consumes g_P0 as a degenerate LC layer: CIN=54, 1x1 "kernel".
    lc_gemm_body<54, 1, 1, 20, 20, 32, 32, 54>(g_P0, W, b, g_H0);
}
__global__ void __launch_bounds__(256) k_l1(const float* __restrict__ W,
                                            const float* __restrict__ b) {
    lc_gemm_body<32, 2, 2, 20, 10, 64, 64, 32>(g_H0, W, b, g_H1);
}
__global__ void __launch_bounds__(256) k_l2(const float* __restrict__ W,
                                            const float* __restrict__ b) {
    lc_gemm_body<64, 5, 5, 10, 2, 128, 64, 50>(g_H1, W, b, g_H2);
}

// ---------------------------------------------------------------------------
// Classifier + softmax.
// flatten index f (of [B,128,2,2]) = c*4 + loc2; g_H2 addr = (loc2*128+c)*B+b.
// ---------------------------------------------------------------------------
__global__ void __launch_bounds__(256) classifier_k(const float* __restrict__ info,
                                                    const float* __restrict__ Wc,
                                                    const float* __restrict__ bc,
                                                    float* __restrict__ out) {
    __shared__ float wsm[514 * 2 + 2];
    for (int e = threadIdx.x; e < 1028; e += 256) wsm[e] = Wc[e];
    if (threadIdx.x < 2) wsm[1028 + threadIdx.x] = bc[threadIdx.x];
    __syncthreads();

    const int b = blockIdx.x * 256 + threadIdx.x;
    float l0 = wsm[1028], l1 = wsm[1029];
#pragma unroll 8
    for (int f = 0; f < 512; f++) {
        float hv = g_H2[(size_t)((f & 3) * 128 + (f >> 2)) * 4096 + b];
        l0 += hv * wsm[f * 2];
        l1 += hv * wsm[f * 2 + 1];
    }
    float i0 = info[2 * b], i1 = info[2 * b + 1];
    l0 += i0 * wsm[512 * 2]     + i1 * wsm[513 * 2];
    l1 += i0 * wsm[512 * 2 + 1] + i1 * wsm[513 * 2 + 1];

    float m = fmaxf(l0, l1);
    float e0 = __expf(l0 - m), e1 = __expf(l1 - m);
    float inv = 1.0f / (e0 + e1);
    ((float2*)out)[b] = make_float2(e0 * inv, e1 * inv);
}

extern "C" void kernel_launch(void* const* d_in, const int* in_sizes, int n_in,
                              void* d_out, int out_size) {
    const float* x    = (const float*)d_in[0];
    const float* info = (const float*)d_in[1];
    const float* W0   = (const float*)d_in[2];
    const float* B0   = (const float*)d_in[3];
    const float* W1   = (const float*)d_in[4];
    const float* B1   = (const float*)d_in[5];
    const float* W2   = (const float*)d_in[6];
    const float* B2   = (const float*)d_in[7];
    const float* Wc   = (const float*)d_in[8];
    const float* bc   = (const float*)d_in[9];
    float* out = (float*)d_out;

    im2col_k<<<dim3(360, 128), 256>>>(x);
    k_l0<<<dim3(400, 32, 1), 256>>>(W0, B0);
    k_l1<<<dim3(100, 32, 1), 256>>>(W1, B1);
    k_l2<<<dim3(4, 32, 2), 256>>>(W2, B2);
    classifier_k<<<16, 256>>>(info, Wc, bc, out);
}

// round 2
// speedup vs baseline: 1.3677x; 1.3677x over previous
#include <cuda_runtime.h>
#include <cuda_bf16.h>
#include <cstdint>

// Scratch in static device memory. Layouts: [location][channel/k][batch], batch innermost.
__device__ float g_P0[400 * 54 * 4096];   // im2col of x
__device__ float g_H0[400 * 32 * 4096];   // layer0 out
__device__ float g_H1[100 * 64 * 4096];   // layer1 out
__device__ float g_H2[4 * 128 * 4096];    // layer2 out
__device__ float g_PART[4 * 4 * 128 * 4096]; // layer2 split-K partials [kz][loc][co][b]

static __device__ __forceinline__ float tanhap(float x) {
    float y; asm("tanh.approx.f32 %0, %1;" : "=f"(y) : "f"(x)); return y;
}
static __device__ __forceinline__ unsigned long long pack2(float w) {
    unsigned long long p; asm("mov.b64 %0, {%1, %1};" : "=l"(p) : "f"(w)); return p;
}
static __device__ __forceinline__ void ffma2(unsigned long long& acc,
                                             unsigned long long a, unsigned long long w2) {
    asm("fma.rn.f32x2 %0, %1, %2, %0;" : "+l"(acc) : "l"(a), "l"(w2));
}
static __device__ __forceinline__ void cpa16(void* s, const void* g) {
    uint32_t sa = (uint32_t)__cvta_generic_to_shared(s);
    asm volatile("cp.async.ca.shared.global [%0], [%1], 16;" :: "r"(sa), "l"(g));
}
static __device__ __forceinline__ void cpa4(void* s, const void* g) {
    uint32_t sa = (uint32_t)__cvta_generic_to_shared(s);
    asm volatile("cp.async.ca.shared.global [%0], [%1], 4;" :: "r"(sa), "l"(g));
}
static __device__ __forceinline__ void cpa_wait() {
    asm volatile("cp.async.commit_group;");
    asm volatile("cp.async.wait_group 0;");
}

// ---------------------------------------------------------------------------
// im2col: x[B,6,60,60] -> g_P0[loc][k][B]
// ---------------------------------------------------------------------------
__global__ void __launch_bounds__(256) im2col_k(const float* __restrict__ x) {
    const int ch = blockIdx.x;          // 0..359
    const int c = ch / 60, h = ch % 60;
    const int b0 = blockIdx.y * 32;
    __shared__ float s[32 * 61];
    const float* src = x + ((size_t)b0 * 6 + c) * 3600 + (size_t)h * 60;
    for (int e = threadIdx.x; e < 32 * 60; e += 256) {
        int bl = e / 60, w = e - bl * 60;
        s[bl * 61 + w] = src[(size_t)bl * 21600 + w];
    }
    __syncthreads();
    const int i = h / 3, dh = h % 3;
    for (int e = threadIdx.x; e < 32 * 60; e += 256) {
        int w = e >> 5, bl = e & 31;
        int j = w / 3, dw = w - j * 3;
        g_P0[((size_t)(i * 20 + j) * 54 + c * 9 + dh * 3 + dw) * 4096 + b0 + bl] =
            s[bl * 61 + w];
    }
}

// ---------------------------------------------------------------------------
// Locally-connected GEMM layer. 256 threads. Block tile: BB batches x COUT_BLK couts.
// Thread: lane (batch pairs), cgrp = cout group of NC=COUT_BLK/8.
// PARTIAL: no bias/tanh, write raw sums offset by kz*KZSTRIDE.
// ---------------------------------------------------------------------------
template <int CIN, int KH, int KW, int WIN, int WOUT, int COUT, int COUT_BLK,
          int KCHUNK, int BB, int KSPLIT, bool PARTIAL, int KZSTRIDE, bool W16>
static __device__ __forceinline__ void lc_gemm_body(const float* __restrict__ in,
                                                    const float* __restrict__ W,
                                                    const float* __restrict__ bias,
                                                    float* __restrict__ out) {
    constexpr int K    = CIN * KH * KW;
    constexpr int KPER = K / KSPLIT;
    constexpr int NC   = COUT_BLK / 8;
    constexpr int NB2  = BB / 64;       // u64 batch-pairs per thread
    constexpr int B    = 4096;

    __shared__ __align__(16) float as[KCHUNK * BB];
    __shared__ __align__(16) float ws[COUT_BLK * KCHUNK];

    const int loc = blockIdx.x;
    const int i = loc / WOUT, j = loc - i * WOUT;
    const int b0 = blockIdx.y * BB;
    const int cz = (blockIdx.z / KSPLIT) * COUT_BLK;
    const int kz = blockIdx.z % KSPLIT;
    const int t = threadIdx.x;
    const int lane = t & 31;
    const int cgrp = t >> 5;

    const float* Wl = W + ((size_t)loc * COUT + cz) * K;
    float* ob = out + (size_t)kz * KZSTRIDE;

    unsigned long long acc[NC][NB2];
#pragma unroll
    for (int c = 0; c < NC; c++) {
        unsigned long long p = PARTIAL ? 0ull
            : pack2(bias[(size_t)loc * COUT + cz + cgrp * NC + c]);
#pragma unroll
        for (int p2 = 0; p2 < NB2; p2++) acc[c][p2] = p;
    }

    const int kbeg = kz * KPER, kend = kbeg + KPER;
    for (int k0 = kbeg; k0 < kend; k0 += KCHUNK) {
        // W tile
        if (W16) {
            for (int id = t; id < COUT_BLK * KCHUNK / 4; id += 256) {
                int co = id / (KCHUNK / 4), off = (id % (KCHUNK / 4)) * 4;
                cpa16(&ws[co * KCHUNK + off], Wl + (size_t)co * K + k0 + off);
            }
        } else {
            for (int id = t; id < COUT_BLK * KCHUNK; id += 256) {
                int co = id / KCHUNK, kc = id - co * KCHUNK;
                cpa4(&ws[id], Wl + (size_t)co * K + k0 + kc);
            }
        }
        // A tile: rows are contiguous BB-float runs in `in`
        for (int id = t; id < KCHUNK * BB / 4; id += 256) {
            int kc = id / (BB / 4), off = (id % (BB / 4)) * 4;
            int k = k0 + kc;
            int c = k / (KH * KW);
            int r = k - c * (KH * KW);
            int dh = r / KW, dw = r - dh * KW;
            int loc_in = (KH * i + dh) * WIN + KW * j + dw;
            cpa16(&as[kc * BB + off],
                  in + ((size_t)loc_in * CIN + c) * B + b0 + off);
        }
        cpa_wait();
        __syncthreads();

        const unsigned long long* a2 = (const unsigned long long*)as;
#pragma unroll 2
        for (int kc = 0; kc < KCHUNK; kc++) {
            unsigned long long a[NB2];
#pragma unroll
            for (int p = 0; p < NB2; p++) a[p] = a2[kc * (BB / 2) + p * 32 + lane];
#pragma unroll
            for (int c = 0; c < NC; c++) {
                unsigned long long w2 = pack2(ws[(cgrp * NC + c) * KCHUNK + kc]);
#pragma unroll
                for (int p = 0; p < NB2; p++) ffma2(acc[c][p], a[p], w2);
            }
        }
        __syncthreads();
    }

#pragma unroll
    for (int c = 0; c < NC; c++) {
        size_t obase = ((size_t)loc * COUT + cz + cgrp * NC + c) * B + b0;
#pragma unroll
        for (int p = 0; p < NB2; p++) {
            float x0, x1;
            asm("mov.b64 {%0, %1}, %2;" : "=f"(x0), "=f"(x1) : "l"(acc[c][p]));
            if (!PARTIAL) { x0 = tanhap(x0); x1 = tanhap(x1); }
            ((float2*)(ob + obase + p * 64))[lane] = make_float2(x0, x1);
        }
    }
}

__global__ void __launch_bounds__(256) k_l0(const float* __restrict__ W,
                                            const float* __restrict__ b) {
    // degenerate LC: CIN=54, 1x1 kernel -> reads g_P0[loc][k][B]
    lc_gemm_body<54, 1, 1, 20, 20, 32, 32, 54, 256, 1, false, 0, false>(g_P0, W, b, g_H0);
}
__global__ void __launch_bounds__(256) k_l1(const float* __restrict__ W,
                                            const float* __restrict__ b) {
    lc_gemm_body<32, 2, 2, 20, 10, 64, 64, 64, 128, 1, false, 0, true>(g_H0, W, b, g_H1);
}
__global__ void __launch_bounds__(256) k_l2(const float* __restrict__ W,
                                            const float* __restrict__ b) {
    // split-K=4, partial sums to g_PART
    lc_gemm_body<64, 5, 5, 10, 2, 128, 64, 40, 128, 4, true, 4 * 128 * 4096, true>(
        g_H1, W, b, g_PART);
}

// Reduce split-K partials + bias + tanh -> g_H2
__global__ void __launch_bounds__(256) l2_combine_k(const float* __restrict__ B2) {
    constexpr int ST = 4 * 128 * 4096;
    int idx = blockIdx.x * 256 + threadIdx.x;     // over 4*128*4096
    int row = idx >> 12;                          // loc*128 + co  (B2 is [loc2][co])
    float s = B2[row] + g_PART[idx] + g_PART[idx + ST]
            + g_PART[idx + 2 * ST] + g_PART[idx + 3 * ST];
    g_H2[idx] = tanhap(s);
}

// ---------------------------------------------------------------------------
// Classifier + softmax. 128 blocks x 256 threads: 32 batches x 8 f-groups.
// flatten f = c*4 + loc2; g_H2 row = loc2*128 + c = (f&3)*128 + (f>>2).
// ---------------------------------------------------------------------------
__global__ void __launch_bounds__(256) classifier_k(const float* __restrict__ info,
                                                    const float* __restrict__ Wc,
                                                    const float* __restrict__ bc,
                                                    float* __restrict__ out) {
    __shared__ float wsm[1030];
    __shared__ float red[8][32][2];
    for (int e = threadIdx.x; e < 1028; e += 256) wsm[e] = Wc[e];
    if (threadIdx.x < 2) wsm[1028 + threadIdx.x] = bc[threadIdx.x];
    __syncthreads();

    const int fg = threadIdx.x >> 5, lane = threadIdx.x & 31;
    const int b = blockIdx.x * 32 + lane;
    float l0 = 0.f, l1 = 0.f;
#pragma unroll 8
    for (int ff = 0; ff < 64; ff++) {
        int f = fg * 64 + ff;
        int row = (f & 3) * 128 + (f >> 2);
        float hv = g_H2[(size_t)row * 4096 + b];
        l0 += hv * wsm[f * 2];
        l1 += hv * wsm[f * 2 + 1];
    }
    red[fg][lane][0] = l0;
    red[fg][lane][1] = l1;
    __syncthreads();

    if (threadIdx.x < 32) {
        int bb = blockIdx.x * 32 + threadIdx.x;
        float s0 = wsm[1028], s1 = wsm[1029];
#pragma unroll
        for (int g = 0; g < 8; g++) { s0 += red[g][threadIdx.x][0]; s1 += red[g][threadIdx.x][1]; }
        float i0 = info[2 * bb], i1 = info[2 * bb + 1];
        s0 += i0 * wsm[512 * 2]     + i1 * wsm[513 * 2];
        s1 += i0 * wsm[512 * 2 + 1] + i1 * wsm[513 * 2 + 1];
        float m = fmaxf(s0, s1);
        float e0 = __expf(s0 - m), e1 = __expf(s1 - m);
        float inv = 1.0f / (e0 + e1);
        ((float2*)out)[bb] = make_float2(e0 * inv, e1 * inv);
    }
}

extern "C" void kernel_launch(void* const* d_in, const int* in_sizes, int n_in,
                              void* d_out, int out_size) {
    const float* x    = (const float*)d_in[0];
    const float* info = (const float*)d_in[1];
    const float* W0   = (const float*)d_in[2];
    const float* B0   = (const float*)d_in[3];
    const float* W1   = (const float*)d_in[4];
    const float* B1   = (const float*)d_in[5];
    const float* W2   = (const float*)d_in[6];
    const float* B2   = (const float*)d_in[7];
    const float* Wc   = (const float*)d_in[8];
    const float* bc   = (const float*)d_in[9];
    float* out = (float*)d_out;

    im2col_k<<<dim3(360, 128), 256>>>(x);
    k_l0<<<dim3(400, 16, 1), 256>>>(W0, B0);             // 6400 blocks
    k_l1<<<dim3(100, 32, 1), 256>>>(W1, B1);             // 3200 blocks
    k_l2<<<dim3(4, 32, 8), 256>>>(W2, B2);               // 1024 blocks (2 cout x 4 ksplit)
    l2_combine_k<<<4 * 128 * 4096 / 256, 256>>>(B2);
    classifier_k<<<128, 256>>>(info, Wc, bc, out);
}